// round 8
// baseline (speedup 1.0000x reference)
#include <cuda_runtime.h>
#include <cuda_bf16.h>
#include <cstdint>

#define NB   8
#define SEQ  2048
#define DIM  1024
#define HS   64

// ---------------- device scratch (no cudaMalloc allowed) ----------------
__device__ __nv_bfloat16 g_qh [NB * SEQ * HS];   // q*(0.125*log2e) hi, [b][s][h]
__device__ __nv_bfloat16 g_ql [NB * SEQ * HS];
__device__ __nv_bfloat16 g_kh [NB * SEQ * HS];   // k hi, [b][s][h]
__device__ __nv_bfloat16 g_kl [NB * SEQ * HS];
__device__ __nv_bfloat16 g_vth[NB * HS * SEQ];   // v^T hi: [b][h][s]
__device__ __nv_bfloat16 g_vtl[NB * HS * SEQ];
__device__ __nv_bfloat16 g_wth[3 * HS * DIM];    // W^T hi: [mode][n][k]
__device__ __nv_bfloat16 g_wtl[3 * HS * DIM];

// split-KV partials: 2 halves per (b, qtile)
#define NPART (NB * 16 * 2)
__device__ float g_pO[NPART][128][64];           // unnormalized partial O
__device__ float g_pm[NPART][128];               // row max (log2 domain)
__device__ float g_pl[NPART][128];               // row sum

// ---------------- helpers ----------------
__device__ __forceinline__ uint32_t s2u(const void* p) {
    uint32_t a;
    asm("{ .reg .u64 t; cvta.to.shared.u64 t, %1; cvt.u32.u64 %0, t; }" : "=r"(a) : "l"(p));
    return a;
}
__device__ __forceinline__ void fsplit(float a, __nv_bfloat16& h, __nv_bfloat16& l) {
    h = __float2bfloat16(a);
    l = __float2bfloat16(a - __bfloat162float(h));
}
__device__ __forceinline__ uint32_t pack2(__nv_bfloat16 a, __nv_bfloat16 b) {
    __nv_bfloat162 v = __halves2bfloat162(a, b);
    return *reinterpret_cast<uint32_t*>(&v);
}
__device__ __forceinline__ float ex2(float x) {
    float y;
    asm("ex2.approx.f32 %0, %1;" : "=f"(y) : "f"(x));
    return y;
}
__device__ __forceinline__ void ldsm4(uint32_t r[4], uint32_t addr) {
    asm volatile("ldmatrix.sync.aligned.m8n8.x4.shared.b16 {%0,%1,%2,%3}, [%4];"
                 : "=r"(r[0]), "=r"(r[1]), "=r"(r[2]), "=r"(r[3]) : "r"(addr));
}
__device__ __forceinline__ void mma_bf16(float d[4], const uint32_t a[4], const uint32_t b[2]) {
    asm volatile("mma.sync.aligned.m16n8k16.row.col.f32.bf16.bf16.f32 "
                 "{%0,%1,%2,%3},{%4,%5,%6,%7},{%8,%9},{%0,%1,%2,%3};"
                 : "+f"(d[0]), "+f"(d[1]), "+f"(d[2]), "+f"(d[3])
                 : "r"(a[0]), "r"(a[1]), "r"(a[2]), "r"(a[3]), "r"(b[0]), "r"(b[1]));
}
__device__ __forceinline__ void cpa16(uint32_t saddr, const void* gaddr) {
    asm volatile("cp.async.cg.shared.global [%0], [%1], 16;" :: "r"(saddr), "l"(gaddr));
}
#define CP_COMMIT() asm volatile("cp.async.commit_group;" ::: "memory")
#define CP_WAIT1()  asm volatile("cp.async.wait_group 1;" ::: "memory")
#define CP_WAIT0()  asm volatile("cp.async.wait_group 0;" ::: "memory")

// =================================================================
// Kernel 1: W -> W^T bf16 hi/lo. Wq pre-scaled by 0.125*log2(e).
// =================================================================
__global__ void prep_w(const float* __restrict__ Wq, const float* __restrict__ Wk,
                       const float* __restrict__ Wv)
{
    int mode = blockIdx.y;
    const float* W = (mode == 0) ? Wq : ((mode == 1) ? Wk : Wv);
    float sc = (mode == 0) ? 0.18033688011112042f : 1.0f;   // 0.125 * log2(e)
    int t = blockIdx.x * 256 + threadIdx.x;      // 0..65535
    int k = t & 1023, n = t >> 10;
    float x = W[(size_t)k * HS + n] * sc;
    __nv_bfloat16 h, l;
    fsplit(x, h, l);
    g_wth[((size_t)mode * HS + n) * DIM + k] = h;
    g_wtl[((size_t)mode * HS + n) * DIM + k] = l;
}

// =================================================================
// Kernel 2: projections via mma.sync bf16-split (unchanged).
// =================================================================
#define PST 40

__global__ __launch_bounds__(256) void proj_mma(
    const float* __restrict__ Xq, const float* __restrict__ Xk, const float* __restrict__ Xv)
{
    __shared__ __align__(16) __nv_bfloat16 sAh[128 * PST];
    __shared__ __align__(16) __nv_bfloat16 sAl[128 * PST];
    __shared__ __align__(16) __nv_bfloat16 sBh[64 * PST];
    __shared__ __align__(16) __nv_bfloat16 sBl[64 * PST];

    const int tid = threadIdx.x;
    const int lane = tid & 31, w = tid >> 5;
    const int mode = blockIdx.y;
    const int row0 = blockIdx.x * 128;

    const float* X = (mode == 0) ? Xq : ((mode == 1) ? Xk : Xv);
    const __nv_bfloat16* WTh = g_wth + (size_t)mode * HS * DIM;
    const __nv_bfloat16* WTl = g_wtl + (size_t)mode * HS * DIM;

    const uint32_t aBase = s2u(sAh), alBase = s2u(sAl);
    const uint32_t bBase = s2u(sBh), blBase = s2u(sBl);
    const uint32_t laneA = (uint32_t)((((lane & 7) + (((lane >> 3) & 1) << 3)) * PST + ((lane >> 4) << 3)) * 2);
    const uint32_t laneB = (uint32_t)((((lane & 7) + ((lane >> 4) << 3)) * PST + (((lane >> 3) & 1) << 3)) * 2);

    float acc[8][4];
#pragma unroll
    for (int nt = 0; nt < 8; nt++)
#pragma unroll
        for (int e = 0; e < 4; e++) acc[nt][e] = 0.0f;

    float4 fa[4];
    uint4 wbh, wbl;
    const int bn = tid >> 2, bq = tid & 3;

#pragma unroll
    for (int it = 0; it < 4; it++) {
        int idx = tid + it * 256, m = idx >> 3, kq = idx & 7;
        fa[it] = *(const float4*)(X + (size_t)(row0 + m) * DIM + kq * 4);
    }
    wbh = *(const uint4*)(WTh + (size_t)bn * DIM + bq * 8);
    wbl = *(const uint4*)(WTl + (size_t)bn * DIM + bq * 8);

    for (int kb = 0; kb < 32; kb++) {
#pragma unroll
        for (int it = 0; it < 4; it++) {
            int idx = tid + it * 256, m = idx >> 3, kq = idx & 7;
            __nv_bfloat16 h0, h1, h2, h3, l0, l1, l2, l3;
            fsplit(fa[it].x, h0, l0); fsplit(fa[it].y, h1, l1);
            fsplit(fa[it].z, h2, l2); fsplit(fa[it].w, h3, l3);
            *(uint2*)(sAh + m * PST + kq * 4) = make_uint2(pack2(h0, h1), pack2(h2, h3));
            *(uint2*)(sAl + m * PST + kq * 4) = make_uint2(pack2(l0, l1), pack2(l2, l3));
        }
        *(uint4*)(sBh + bn * PST + bq * 8) = wbh;
        *(uint4*)(sBl + bn * PST + bq * 8) = wbl;
        __syncthreads();

        if (kb + 1 < 32) {
            int kc = (kb + 1) * 32;
#pragma unroll
            for (int it = 0; it < 4; it++) {
                int idx = tid + it * 256, m = idx >> 3, kq = idx & 7;
                fa[it] = *(const float4*)(X + (size_t)(row0 + m) * DIM + kc + kq * 4);
            }
            wbh = *(const uint4*)(WTh + (size_t)bn * DIM + kc + bq * 8);
            wbl = *(const uint4*)(WTl + (size_t)bn * DIM + kc + bq * 8);
        }

#pragma unroll
        for (int ks = 0; ks < 2; ks++) {
            uint32_t ah[4], al_[4];
            ldsm4(ah,  aBase  + (uint32_t)((w * 16 * PST + ks * 16) * 2) + laneA);
            ldsm4(al_, alBase + (uint32_t)((w * 16 * PST + ks * 16) * 2) + laneA);
            uint32_t bh[16], bl[16];
#pragma unroll
            for (int p = 0; p < 4; p++) {
                ldsm4(&bh[p * 4], bBase  + (uint32_t)((p * 16 * PST + ks * 16) * 2) + laneB);
                ldsm4(&bl[p * 4], blBase + (uint32_t)((p * 16 * PST + ks * 16) * 2) + laneB);
            }
#pragma unroll
            for (int nt = 0; nt < 8; nt++) {
                const uint32_t* bph = &bh[(nt >> 1) * 4 + (nt & 1) * 2];
                const uint32_t* bpl = &bl[(nt >> 1) * 4 + (nt & 1) * 2];
                mma_bf16(acc[nt], ah, bph);
                mma_bf16(acc[nt], ah, bpl);
                mma_bf16(acc[nt], al_, bph);
            }
        }
        __syncthreads();
    }

    const int rl = row0 + w * 16 + (lane >> 2);
    if (mode == 2) {
        const int b = rl / SEQ, s = rl % SEQ;
#pragma unroll
        for (int nt = 0; nt < 8; nt++) {
            int c = nt * 8 + (lane & 3) * 2;
#pragma unroll
            for (int e = 0; e < 2; e++) {
                __nv_bfloat16 h, l;
                fsplit(acc[nt][e], h, l);
                g_vth[((size_t)b * HS + c + e) * SEQ + s] = h;
                g_vtl[((size_t)b * HS + c + e) * SEQ + s] = l;
                fsplit(acc[nt][2 + e], h, l);
                g_vth[((size_t)b * HS + c + e) * SEQ + s + 8] = h;
                g_vtl[((size_t)b * HS + c + e) * SEQ + s + 8] = l;
            }
        }
    } else {
        __nv_bfloat16* Oh = mode ? g_kh : g_qh;
        __nv_bfloat16* Ol = mode ? g_kl : g_ql;
#pragma unroll
        for (int nt = 0; nt < 8; nt++) {
            int c = nt * 8 + (lane & 3) * 2;
            __nv_bfloat16 h0, l0, h1, l1;
            fsplit(acc[nt][0], h0, l0); fsplit(acc[nt][1], h1, l1);
            *(uint32_t*)(Oh + (size_t)rl * HS + c) = pack2(h0, h1);
            *(uint32_t*)(Ol + (size_t)rl * HS + c) = pack2(l0, l1);
            fsplit(acc[nt][2], h0, l0); fsplit(acc[nt][3], h1, l1);
            *(uint32_t*)(Oh + (size_t)(rl + 8) * HS + c) = pack2(h0, h1);
            *(uint32_t*)(Ol + (size_t)(rl + 8) * HS + c) = pack2(l0, l1);
        }
    }
}

// =================================================================
// Kernel 3: split-KV causal flash attention, 2 blocks/SM.
// Q fragments reloaded from smem each tile (frees 32 regs so
// __launch_bounds__(256,2) compiles without spills).
// =================================================================
#define AST 72
#define OFF_QH 0
#define OFF_QL 18432
#define OFF_BUF 36864
#define BUF_STRIDE 36864
#define ARR_STRIDE 9216
#define ATTN_SMEM 110592

__global__ __launch_bounds__(256, 2) void attn_mma()
{
    extern __shared__ __align__(16) char sm[];
    const uint32_t sb = s2u(sm);
    const int tid = threadIdx.x, lane = tid & 31, w = tid >> 5;
    const int b = blockIdx.y;
    const int qt   = 15 - ((int)blockIdx.x >> 1);
    const int half = (int)blockIdx.x & 1;
    const int k0 = half ? (qt + 1) : 0;
    const int k1 = half ? (2 * qt + 2) : (qt + 1);
    const int part = ((b * 16 + qt) * 2) + half;

    const __nv_bfloat16* Qh  = g_qh + ((size_t)b * SEQ + qt * 128) * HS;
    const __nv_bfloat16* Ql  = g_ql + ((size_t)b * SEQ + qt * 128) * HS;
    const __nv_bfloat16* Kh0 = g_kh + (size_t)b * SEQ * HS;
    const __nv_bfloat16* Kl0 = g_kl + (size_t)b * SEQ * HS;
    const __nv_bfloat16* Vh0 = g_vth + (size_t)b * HS * SEQ;
    const __nv_bfloat16* Vl0 = g_vtl + (size_t)b * HS * SEQ;

#pragma unroll
    for (int it = 0; it < 4; it++) {
        int idx = tid + it * 256, r = idx >> 3, q = idx & 7;
        cpa16(sb + OFF_QH + (r * AST + q * 8) * 2, Qh + (size_t)r * HS + q * 8);
        cpa16(sb + OFF_QL + (r * AST + q * 8) * 2, Ql + (size_t)r * HS + q * 8);
    }
    CP_COMMIT();

    auto issue_kv = [&](int kt, int dst) {
        uint32_t base = sb + OFF_BUF + dst * BUF_STRIDE;
#pragma unroll
        for (int it = 0; it < 8; it++) {
            int idx = tid + it * 256;
            int a = idx >> 9, rem = idx & 511;
            int r = rem >> 3, q = rem & 7;
            const __nv_bfloat16* src;
            if (a == 0)      src = Kh0 + (size_t)(kt * 64 + r) * HS + q * 8;
            else if (a == 1) src = Kl0 + (size_t)(kt * 64 + r) * HS + q * 8;
            else if (a == 2) src = Vh0 + (size_t)r * SEQ + kt * 64 + q * 8;
            else             src = Vl0 + (size_t)r * SEQ + kt * 64 + q * 8;
            cpa16(base + a * ARR_STRIDE + (r * AST + q * 8) * 2, src);
        }
        CP_COMMIT();
    };
    issue_kv(k0, 0);

    const uint32_t laneA = (uint32_t)((((lane & 7) + (((lane >> 3) & 1) << 3)) * AST + ((lane >> 4) << 3)) * 2);
    const uint32_t laneB = (uint32_t)((((lane & 7) + ((lane >> 4) << 3)) * AST + (((lane >> 3) & 1) << 3)) * 2);
    const uint32_t qRow = sb + (uint32_t)((w * 16 * AST) * 2) + laneA;

    float O[8][4];
#pragma unroll
    for (int nt = 0; nt < 8; nt++)
#pragma unroll
        for (int e = 0; e < 4; e++) O[nt][e] = 0.0f;
    float mr0 = -1e30f, mr1 = -1e30f, lr0 = 0.0f, lr1 = 0.0f;

    for (int kt = k0; kt < k1; kt++) {
        const int bf = (kt - k0) & 1;
        if (kt + 1 < k1) { issue_kv(kt + 1, bf ^ 1); CP_WAIT1(); }
        else             { CP_WAIT0(); }
        __syncthreads();

        const uint32_t kbH = sb + OFF_BUF + bf * BUF_STRIDE;
        const uint32_t kbL = kbH + ARR_STRIDE;
        const uint32_t vbH = kbH + 2 * ARR_STRIDE;
        const uint32_t vbL = kbH + 3 * ARR_STRIDE;

        // ---- S = Q K^T (hh + hl + lh), Q frags reloaded per ks ----
        float s[8][4];
#pragma unroll
        for (int nt = 0; nt < 8; nt++)
#pragma unroll
            for (int e = 0; e < 4; e++) s[nt][e] = 0.0f;

#pragma unroll
        for (int ks = 0; ks < 4; ks++) {
            uint32_t qh[4], ql[4];
            ldsm4(qh, qRow + OFF_QH + (uint32_t)(ks * 32));
            ldsm4(ql, qRow + OFF_QL + (uint32_t)(ks * 32));
            uint32_t bh[16], bl[16];
#pragma unroll
            for (int p = 0; p < 4; p++) {
                ldsm4(&bh[p * 4], kbH + (uint32_t)((p * 16 * AST + ks * 16) * 2) + laneB);
                ldsm4(&bl[p * 4], kbL + (uint32_t)((p * 16 * AST + ks * 16) * 2) + laneB);
            }
#pragma unroll
            for (int nt = 0; nt < 8; nt++) {
                const uint32_t* bph = &bh[(nt >> 1) * 4 + (nt & 1) * 2];
                const uint32_t* bpl = &bl[(nt >> 1) * 4 + (nt & 1) * 2];
                mma_bf16(s[nt], qh, bph);
                mma_bf16(s[nt], qh, bpl);
                mma_bf16(s[nt], ql, bph);
            }
        }

        // ---- causal mask (diagonal tiles only) ----
        if (kt >= 2 * qt) {
            int lim = qt * 128 + w * 16 + (lane >> 2) - kt * 64;
#pragma unroll
            for (int nt = 0; nt < 8; nt++) {
                int c = nt * 8 + (lane & 3) * 2;
                if (c     > lim)     s[nt][0] = -1e30f;
                if (c + 1 > lim)     s[nt][1] = -1e30f;
                if (c     > lim + 8) s[nt][2] = -1e30f;
                if (c + 1 > lim + 8) s[nt][3] = -1e30f;
            }
        }

        // ---- online softmax (exp2 domain) ----
        float rm0 = -1e30f, rm1 = -1e30f;
#pragma unroll
        for (int nt = 0; nt < 8; nt++) {
            rm0 = fmaxf(rm0, fmaxf(s[nt][0], s[nt][1]));
            rm1 = fmaxf(rm1, fmaxf(s[nt][2], s[nt][3]));
        }
        rm0 = fmaxf(rm0, __shfl_xor_sync(0xffffffffu, rm0, 1));
        rm0 = fmaxf(rm0, __shfl_xor_sync(0xffffffffu, rm0, 2));
        rm1 = fmaxf(rm1, __shfl_xor_sync(0xffffffffu, rm1, 1));
        rm1 = fmaxf(rm1, __shfl_xor_sync(0xffffffffu, rm1, 2));
        float mn0 = fmaxf(mr0, rm0), mn1 = fmaxf(mr1, rm1);
        float al0 = ex2(mr0 - mn0), al1 = ex2(mr1 - mn1);
        mr0 = mn0; mr1 = mn1;

        float rs0 = 0.0f, rs1 = 0.0f;
#pragma unroll
        for (int nt = 0; nt < 8; nt++) {
            s[nt][0] = ex2(s[nt][0] - mn0);
            s[nt][1] = ex2(s[nt][1] - mn0);
            s[nt][2] = ex2(s[nt][2] - mn1);
            s[nt][3] = ex2(s[nt][3] - mn1);
            rs0 += s[nt][0] + s[nt][1];
            rs1 += s[nt][2] + s[nt][3];
        }
        rs0 += __shfl_xor_sync(0xffffffffu, rs0, 1);
        rs0 += __shfl_xor_sync(0xffffffffu, rs0, 2);
        rs1 += __shfl_xor_sync(0xffffffffu, rs1, 1);
        rs1 += __shfl_xor_sync(0xffffffffu, rs1, 2);
        lr0 = lr0 * al0 + rs0;
        lr1 = lr1 * al1 + rs1;
#pragma unroll
        for (int nt = 0; nt < 8; nt++) {
            O[nt][0] *= al0; O[nt][1] *= al0;
            O[nt][2] *= al1; O[nt][3] *= al1;
        }

        // ---- P (C-frag) -> A-frag bf16 hi/lo ----
        uint32_t ph[4][4], pl[4][4];
#pragma unroll
        for (int ks = 0; ks < 4; ks++) {
            int t0 = 2 * ks, t1 = 2 * ks + 1;
            __nv_bfloat16 ha, la, hb, lb;
            fsplit(s[t0][0], ha, la); fsplit(s[t0][1], hb, lb);
            ph[ks][0] = pack2(ha, hb); pl[ks][0] = pack2(la, lb);
            fsplit(s[t0][2], ha, la); fsplit(s[t0][3], hb, lb);
            ph[ks][1] = pack2(ha, hb); pl[ks][1] = pack2(la, lb);
            fsplit(s[t1][0], ha, la); fsplit(s[t1][1], hb, lb);
            ph[ks][2] = pack2(ha, hb); pl[ks][2] = pack2(la, lb);
            fsplit(s[t1][2], ha, la); fsplit(s[t1][3], hb, lb);
            ph[ks][3] = pack2(ha, hb); pl[ks][3] = pack2(la, lb);
        }

        // ---- O += P @ V (hh + hl + lh) ----
#pragma unroll
        for (int ks = 0; ks < 4; ks++) {
            uint32_t vh[16], vl[16];
#pragma unroll
            for (int p = 0; p < 4; p++) {
                ldsm4(&vh[p * 4], vbH + (uint32_t)((p * 16 * AST + ks * 16) * 2) + laneB);
                ldsm4(&vl[p * 4], vbL + (uint32_t)((p * 16 * AST + ks * 16) * 2) + laneB);
            }
#pragma unroll
            for (int nt = 0; nt < 8; nt++) {
                const uint32_t* vph = &vh[(nt >> 1) * 4 + (nt & 1) * 2];
                const uint32_t* vpl = &vl[(nt >> 1) * 4 + (nt & 1) * 2];
                mma_bf16(O[nt], ph[ks], vph);
                mma_bf16(O[nt], pl[ks], vph);
                mma_bf16(O[nt], ph[ks], vpl);
            }
        }
        __syncthreads();
    }

    // ---- epilogue: unnormalized partials ----
    int r0 = w * 16 + (lane >> 2);
#pragma unroll
    for (int nt = 0; nt < 8; nt++) {
        int c = nt * 8 + (lane & 3) * 2;
        *(float2*)(&g_pO[part][r0][c])     = make_float2(O[nt][0], O[nt][1]);
        *(float2*)(&g_pO[part][r0 + 8][c]) = make_float2(O[nt][2], O[nt][3]);
    }
    if ((lane & 3) == 0) {
        g_pm[part][r0] = mr0;     g_pl[part][r0] = lr0;
        g_pm[part][r0 + 8] = mr1; g_pl[part][r0 + 8] = lr1;
    }
}

// =================================================================
// Kernel 4: combine. 512 blocks x 256 thr; 8 threads/row, 8 cols each.
// =================================================================
__global__ __launch_bounds__(256) void combine(float* __restrict__ out)
{
    const int pair  = blockIdx.x >> 2;           // b*16 + qt
    const int chunk = blockIdx.x & 3;
    const int r = chunk * 32 + (threadIdx.x >> 3);
    const int c = (threadIdx.x & 7) * 8;
    const int p0 = pair * 2, p1 = p0 + 1;

    float m0 = g_pm[p0][r], l0 = g_pl[p0][r];
    float m1 = g_pm[p1][r], l1 = g_pl[p1][r];
    float M  = fmaxf(m0, m1);
    float w0 = ex2(m0 - M), w1 = ex2(m1 - M);
    float inv = 1.0f / (w0 * l0 + w1 * l1);
    float c0 = w0 * inv, c1 = w1 * inv;

    const int b = pair >> 4, qt = pair & 15;
    float* op = out + ((size_t)b * SEQ + qt * 128 + r) * HS + c;
#pragma unroll
    for (int u = 0; u < 2; u++) {
        float4 a = *(const float4*)(&g_pO[p0][r][c + u * 4]);
        float4 d = *(const float4*)(&g_pO[p1][r][c + u * 4]);
        *(float4*)(op + u * 4) = make_float4(a.x * c0 + d.x * c1, a.y * c0 + d.y * c1,
                                             a.z * c0 + d.z * c1, a.w * c0 + d.w * c1);
    }
}

// =================================================================
extern "C" void kernel_launch(void* const* d_in, const int* in_sizes, int n_in,
                              void* d_out, int out_size)
{
    (void)in_sizes; (void)n_in; (void)out_size;
    const float* query = (const float*)d_in[0];
    const float* key   = (const float*)d_in[1];
    const float* value = (const float*)d_in[2];
    const float* Wq    = (const float*)d_in[3];
    const float* Wk    = (const float*)d_in[4];
    const float* Wv    = (const float*)d_in[5];

    prep_w<<<dim3(256, 3, 1), 256>>>(Wq, Wk, Wv);

    proj_mma<<<dim3(128, 3, 1), 256>>>(query, key, value);

    cudaFuncSetAttribute(attn_mma, cudaFuncAttributeMaxDynamicSharedMemorySize, ATTN_SMEM);
    attn_mma<<<dim3(32, NB, 1), 256, ATTN_SMEM>>>();

    combine<<<NB * 16 * 4, 256>>>((float*)d_out);
}

// round 9
// speedup vs baseline: 1.0075x; 1.0075x over previous
#include <cuda_runtime.h>
#include <cuda_bf16.h>
#include <cstdint>

#define NB   8
#define SEQ  2048
#define DIM  1024
#define HS   64

// ---------------- device scratch (no cudaMalloc allowed) ----------------
__device__ __nv_bfloat16 g_qh [NB * SEQ * HS];   // q*(0.125*log2e) hi, [b][s][h]
__device__ __nv_bfloat16 g_ql [NB * SEQ * HS];
__device__ __nv_bfloat16 g_kh [NB * SEQ * HS];   // k hi, [b][s][h]
__device__ __nv_bfloat16 g_kl [NB * SEQ * HS];
__device__ __nv_bfloat16 g_vth[NB * HS * SEQ];   // v^T hi: [b][h][s]
__device__ __nv_bfloat16 g_vtl[NB * HS * SEQ];
__device__ __nv_bfloat16 g_wth[3 * HS * DIM];    // W^T hi: [mode][n][k]
__device__ __nv_bfloat16 g_wtl[3 * HS * DIM];

// split-KV partials: 2 halves per (b, qtile)
#define NPART (NB * 16 * 2)
__device__ float g_pO[NPART][128][64];           // unnormalized partial O
__device__ float g_pm[NPART][128];               // row max (log2 domain)
__device__ float g_pl[NPART][128];               // row sum

// ---------------- helpers ----------------
__device__ __forceinline__ uint32_t s2u(const void* p) {
    uint32_t a;
    asm("{ .reg .u64 t; cvta.to.shared.u64 t, %1; cvt.u32.u64 %0, t; }" : "=r"(a) : "l"(p));
    return a;
}
__device__ __forceinline__ void fsplit(float a, __nv_bfloat16& h, __nv_bfloat16& l) {
    h = __float2bfloat16(a);
    l = __float2bfloat16(a - __bfloat162float(h));
}
__device__ __forceinline__ uint32_t pack2(__nv_bfloat16 a, __nv_bfloat16 b) {
    __nv_bfloat162 v = __halves2bfloat162(a, b);
    return *reinterpret_cast<uint32_t*>(&v);
}
__device__ __forceinline__ float ex2(float x) {
    float y;
    asm("ex2.approx.f32 %0, %1;" : "=f"(y) : "f"(x));
    return y;
}
__device__ __forceinline__ void ldsm4(uint32_t r[4], uint32_t addr) {
    asm volatile("ldmatrix.sync.aligned.m8n8.x4.shared.b16 {%0,%1,%2,%3}, [%4];"
                 : "=r"(r[0]), "=r"(r[1]), "=r"(r[2]), "=r"(r[3]) : "r"(addr));
}
__device__ __forceinline__ void mma_bf16(float d[4], const uint32_t a[4], const uint32_t b[2]) {
    asm volatile("mma.sync.aligned.m16n8k16.row.col.f32.bf16.bf16.f32 "
                 "{%0,%1,%2,%3},{%4,%5,%6,%7},{%8,%9},{%0,%1,%2,%3};"
                 : "+f"(d[0]), "+f"(d[1]), "+f"(d[2]), "+f"(d[3])
                 : "r"(a[0]), "r"(a[1]), "r"(a[2]), "r"(a[3]), "r"(b[0]), "r"(b[1]));
}
__device__ __forceinline__ void cpa16(uint32_t saddr, const void* gaddr) {
    asm volatile("cp.async.cg.shared.global [%0], [%1], 16;" :: "r"(saddr), "l"(gaddr));
}
#define CP_COMMIT() asm volatile("cp.async.commit_group;" ::: "memory")
#define CP_WAIT1()  asm volatile("cp.async.wait_group 1;" ::: "memory")
#define CP_WAIT0()  asm volatile("cp.async.wait_group 0;" ::: "memory")

// =================================================================
// Kernel 1: W -> W^T bf16 hi/lo. Wq pre-scaled by 0.125*log2(e).
// =================================================================
__global__ void prep_w(const float* __restrict__ Wq, const float* __restrict__ Wk,
                       const float* __restrict__ Wv)
{
    int mode = blockIdx.y;
    const float* W = (mode == 0) ? Wq : ((mode == 1) ? Wk : Wv);
    float sc = (mode == 0) ? 0.18033688011112042f : 1.0f;   // 0.125 * log2(e)
    int t = blockIdx.x * 256 + threadIdx.x;      // 0..65535
    int k = t & 1023, n = t >> 10;
    float x = W[(size_t)k * HS + n] * sc;
    __nv_bfloat16 h, l;
    fsplit(x, h, l);
    g_wth[((size_t)mode * HS + n) * DIM + k] = h;
    g_wtl[((size_t)mode * HS + n) * DIM + k] = l;
}

// =================================================================
// Kernel 2: projections via mma.sync bf16-split, 2 blocks/SM.
// =================================================================
#define PST 40

__global__ __launch_bounds__(256, 2) void proj_mma(
    const float* __restrict__ Xq, const float* __restrict__ Xk, const float* __restrict__ Xv)
{
    __shared__ __align__(16) __nv_bfloat16 sAh[128 * PST];
    __shared__ __align__(16) __nv_bfloat16 sAl[128 * PST];
    __shared__ __align__(16) __nv_bfloat16 sBh[64 * PST];
    __shared__ __align__(16) __nv_bfloat16 sBl[64 * PST];

    const int tid = threadIdx.x;
    const int lane = tid & 31, w = tid >> 5;
    const int mode = blockIdx.y;
    const int row0 = blockIdx.x * 128;

    const float* X = (mode == 0) ? Xq : ((mode == 1) ? Xk : Xv);
    const __nv_bfloat16* WTh = g_wth + (size_t)mode * HS * DIM;
    const __nv_bfloat16* WTl = g_wtl + (size_t)mode * HS * DIM;

    const uint32_t aBase = s2u(sAh), alBase = s2u(sAl);
    const uint32_t bBase = s2u(sBh), blBase = s2u(sBl);
    const uint32_t laneA = (uint32_t)((((lane & 7) + (((lane >> 3) & 1) << 3)) * PST + ((lane >> 4) << 3)) * 2);
    const uint32_t laneB = (uint32_t)((((lane & 7) + ((lane >> 4) << 3)) * PST + (((lane >> 3) & 1) << 3)) * 2);

    float acc[8][4];
#pragma unroll
    for (int nt = 0; nt < 8; nt++)
#pragma unroll
        for (int e = 0; e < 4; e++) acc[nt][e] = 0.0f;

    float4 fa[4];
    uint4 wbh, wbl;
    const int bn = tid >> 2, bq = tid & 3;

#pragma unroll
    for (int it = 0; it < 4; it++) {
        int idx = tid + it * 256, m = idx >> 3, kq = idx & 7;
        fa[it] = *(const float4*)(X + (size_t)(row0 + m) * DIM + kq * 4);
    }
    wbh = *(const uint4*)(WTh + (size_t)bn * DIM + bq * 8);
    wbl = *(const uint4*)(WTl + (size_t)bn * DIM + bq * 8);

    for (int kb = 0; kb < 32; kb++) {
#pragma unroll
        for (int it = 0; it < 4; it++) {
            int idx = tid + it * 256, m = idx >> 3, kq = idx & 7;
            __nv_bfloat16 h0, h1, h2, h3, l0, l1, l2, l3;
            fsplit(fa[it].x, h0, l0); fsplit(fa[it].y, h1, l1);
            fsplit(fa[it].z, h2, l2); fsplit(fa[it].w, h3, l3);
            *(uint2*)(sAh + m * PST + kq * 4) = make_uint2(pack2(h0, h1), pack2(h2, h3));
            *(uint2*)(sAl + m * PST + kq * 4) = make_uint2(pack2(l0, l1), pack2(l2, l3));
        }
        *(uint4*)(sBh + bn * PST + bq * 8) = wbh;
        *(uint4*)(sBl + bn * PST + bq * 8) = wbl;
        __syncthreads();

        if (kb + 1 < 32) {
            int kc = (kb + 1) * 32;
#pragma unroll
            for (int it = 0; it < 4; it++) {
                int idx = tid + it * 256, m = idx >> 3, kq = idx & 7;
                fa[it] = *(const float4*)(X + (size_t)(row0 + m) * DIM + kc + kq * 4);
            }
            wbh = *(const uint4*)(WTh + (size_t)bn * DIM + kc + bq * 8);
            wbl = *(const uint4*)(WTl + (size_t)bn * DIM + kc + bq * 8);
        }

#pragma unroll
        for (int ks = 0; ks < 2; ks++) {
            uint32_t ah[4], al_[4];
            ldsm4(ah,  aBase  + (uint32_t)((w * 16 * PST + ks * 16) * 2) + laneA);
            ldsm4(al_, alBase + (uint32_t)((w * 16 * PST + ks * 16) * 2) + laneA);
            uint32_t bh[16], bl[16];
#pragma unroll
            for (int p = 0; p < 4; p++) {
                ldsm4(&bh[p * 4], bBase  + (uint32_t)((p * 16 * PST + ks * 16) * 2) + laneB);
                ldsm4(&bl[p * 4], blBase + (uint32_t)((p * 16 * PST + ks * 16) * 2) + laneB);
            }
#pragma unroll
            for (int nt = 0; nt < 8; nt++) {
                const uint32_t* bph = &bh[(nt >> 1) * 4 + (nt & 1) * 2];
                const uint32_t* bpl = &bl[(nt >> 1) * 4 + (nt & 1) * 2];
                mma_bf16(acc[nt], ah, bph);
                mma_bf16(acc[nt], ah, bpl);
                mma_bf16(acc[nt], al_, bph);
            }
        }
        __syncthreads();
    }

    const int rl = row0 + w * 16 + (lane >> 2);
    if (mode == 2) {
        const int b = rl / SEQ, s = rl % SEQ;
#pragma unroll
        for (int nt = 0; nt < 8; nt++) {
            int c = nt * 8 + (lane & 3) * 2;
#pragma unroll
            for (int e = 0; e < 2; e++) {
                __nv_bfloat16 h, l;
                fsplit(acc[nt][e], h, l);
                g_vth[((size_t)b * HS + c + e) * SEQ + s] = h;
                g_vtl[((size_t)b * HS + c + e) * SEQ + s] = l;
                fsplit(acc[nt][2 + e], h, l);
                g_vth[((size_t)b * HS + c + e) * SEQ + s + 8] = h;
                g_vtl[((size_t)b * HS + c + e) * SEQ + s + 8] = l;
            }
        }
    } else {
        __nv_bfloat16* Oh = mode ? g_kh : g_qh;
        __nv_bfloat16* Ol = mode ? g_kl : g_ql;
#pragma unroll
        for (int nt = 0; nt < 8; nt++) {
            int c = nt * 8 + (lane & 3) * 2;
            __nv_bfloat16 h0, l0, h1, l1;
            fsplit(acc[nt][0], h0, l0); fsplit(acc[nt][1], h1, l1);
            *(uint32_t*)(Oh + (size_t)rl * HS + c) = pack2(h0, h1);
            *(uint32_t*)(Ol + (size_t)rl * HS + c) = pack2(l0, l1);
            fsplit(acc[nt][2], h0, l0); fsplit(acc[nt][3], h1, l1);
            *(uint32_t*)(Oh + (size_t)(rl + 8) * HS + c) = pack2(h0, h1);
            *(uint32_t*)(Ol + (size_t)(rl + 8) * HS + c) = pack2(l0, l1);
        }
    }
}

// =================================================================
// Kernel 3: split-KV causal flash attention, 2 blocks/SM.
// Q frags reloaded per-ks; P conversion folded into the PV ks loop
// (peak live regs < 128 -> no spills at occupancy 2).
// =================================================================
#define AST 72
#define OFF_QH 0
#define OFF_QL 18432
#define OFF_BUF 36864
#define BUF_STRIDE 36864
#define ARR_STRIDE 9216
#define ATTN_SMEM 110592

__global__ __launch_bounds__(256, 2) void attn_mma()
{
    extern __shared__ __align__(16) char sm[];
    const uint32_t sb = s2u(sm);
    const int tid = threadIdx.x, lane = tid & 31, w = tid >> 5;
    const int b = blockIdx.y;
    const int qt   = 15 - ((int)blockIdx.x >> 1);
    const int half = (int)blockIdx.x & 1;
    const int k0 = half ? (qt + 1) : 0;
    const int k1 = half ? (2 * qt + 2) : (qt + 1);
    const int part = ((b * 16 + qt) * 2) + half;

    const __nv_bfloat16* Qh  = g_qh + ((size_t)b * SEQ + qt * 128) * HS;
    const __nv_bfloat16* Ql  = g_ql + ((size_t)b * SEQ + qt * 128) * HS;
    const __nv_bfloat16* Kh0 = g_kh + (size_t)b * SEQ * HS;
    const __nv_bfloat16* Kl0 = g_kl + (size_t)b * SEQ * HS;
    const __nv_bfloat16* Vh0 = g_vth + (size_t)b * HS * SEQ;
    const __nv_bfloat16* Vl0 = g_vtl + (size_t)b * HS * SEQ;

#pragma unroll
    for (int it = 0; it < 4; it++) {
        int idx = tid + it * 256, r = idx >> 3, q = idx & 7;
        cpa16(sb + OFF_QH + (r * AST + q * 8) * 2, Qh + (size_t)r * HS + q * 8);
        cpa16(sb + OFF_QL + (r * AST + q * 8) * 2, Ql + (size_t)r * HS + q * 8);
    }
    CP_COMMIT();

    auto issue_kv = [&](int kt, int dst) {
        uint32_t base = sb + OFF_BUF + dst * BUF_STRIDE;
#pragma unroll
        for (int it = 0; it < 8; it++) {
            int idx = tid + it * 256;
            int a = idx >> 9, rem = idx & 511;
            int r = rem >> 3, q = rem & 7;
            const __nv_bfloat16* src;
            if (a == 0)      src = Kh0 + (size_t)(kt * 64 + r) * HS + q * 8;
            else if (a == 1) src = Kl0 + (size_t)(kt * 64 + r) * HS + q * 8;
            else if (a == 2) src = Vh0 + (size_t)r * SEQ + kt * 64 + q * 8;
            else             src = Vl0 + (size_t)r * SEQ + kt * 64 + q * 8;
            cpa16(base + a * ARR_STRIDE + (r * AST + q * 8) * 2, src);
        }
        CP_COMMIT();
    };
    issue_kv(k0, 0);

    const uint32_t laneA = (uint32_t)((((lane & 7) + (((lane >> 3) & 1) << 3)) * AST + ((lane >> 4) << 3)) * 2);
    const uint32_t laneB = (uint32_t)((((lane & 7) + ((lane >> 4) << 3)) * AST + (((lane >> 3) & 1) << 3)) * 2);
    const uint32_t qRow = sb + (uint32_t)((w * 16 * AST) * 2) + laneA;

    float O[8][4];
#pragma unroll
    for (int nt = 0; nt < 8; nt++)
#pragma unroll
        for (int e = 0; e < 4; e++) O[nt][e] = 0.0f;
    float mr0 = -1e30f, mr1 = -1e30f, lr0 = 0.0f, lr1 = 0.0f;

    for (int kt = k0; kt < k1; kt++) {
        const int bf = (kt - k0) & 1;
        if (kt + 1 < k1) { issue_kv(kt + 1, bf ^ 1); CP_WAIT1(); }
        else             { CP_WAIT0(); }
        __syncthreads();

        const uint32_t kbH = sb + OFF_BUF + bf * BUF_STRIDE;
        const uint32_t kbL = kbH + ARR_STRIDE;
        const uint32_t vbH = kbH + 2 * ARR_STRIDE;
        const uint32_t vbL = kbH + 3 * ARR_STRIDE;

        // ---- S = Q K^T (hh + hl + lh), Q frags reloaded per ks ----
        float s[8][4];
#pragma unroll
        for (int nt = 0; nt < 8; nt++)
#pragma unroll
            for (int e = 0; e < 4; e++) s[nt][e] = 0.0f;

#pragma unroll
        for (int ks = 0; ks < 4; ks++) {
            uint32_t qh[4], ql[4];
            ldsm4(qh, qRow + OFF_QH + (uint32_t)(ks * 32));
            ldsm4(ql, qRow + OFF_QL + (uint32_t)(ks * 32));
            uint32_t bh[16], bl[16];
#pragma unroll
            for (int p = 0; p < 4; p++) {
                ldsm4(&bh[p * 4], kbH + (uint32_t)((p * 16 * AST + ks * 16) * 2) + laneB);
                ldsm4(&bl[p * 4], kbL + (uint32_t)((p * 16 * AST + ks * 16) * 2) + laneB);
            }
#pragma unroll
            for (int nt = 0; nt < 8; nt++) {
                const uint32_t* bph = &bh[(nt >> 1) * 4 + (nt & 1) * 2];
                const uint32_t* bpl = &bl[(nt >> 1) * 4 + (nt & 1) * 2];
                mma_bf16(s[nt], qh, bph);
                mma_bf16(s[nt], qh, bpl);
                mma_bf16(s[nt], ql, bph);
            }
        }

        // ---- causal mask (diagonal tiles only) ----
        if (kt >= 2 * qt) {
            int lim = qt * 128 + w * 16 + (lane >> 2) - kt * 64;
#pragma unroll
            for (int nt = 0; nt < 8; nt++) {
                int c = nt * 8 + (lane & 3) * 2;
                if (c     > lim)     s[nt][0] = -1e30f;
                if (c + 1 > lim)     s[nt][1] = -1e30f;
                if (c     > lim + 8) s[nt][2] = -1e30f;
                if (c + 1 > lim + 8) s[nt][3] = -1e30f;
            }
        }

        // ---- online softmax (exp2 domain) ----
        float rm0 = -1e30f, rm1 = -1e30f;
#pragma unroll
        for (int nt = 0; nt < 8; nt++) {
            rm0 = fmaxf(rm0, fmaxf(s[nt][0], s[nt][1]));
            rm1 = fmaxf(rm1, fmaxf(s[nt][2], s[nt][3]));
        }
        rm0 = fmaxf(rm0, __shfl_xor_sync(0xffffffffu, rm0, 1));
        rm0 = fmaxf(rm0, __shfl_xor_sync(0xffffffffu, rm0, 2));
        rm1 = fmaxf(rm1, __shfl_xor_sync(0xffffffffu, rm1, 1));
        rm1 = fmaxf(rm1, __shfl_xor_sync(0xffffffffu, rm1, 2));
        float mn0 = fmaxf(mr0, rm0), mn1 = fmaxf(mr1, rm1);
        float al0 = ex2(mr0 - mn0), al1 = ex2(mr1 - mn1);
        mr0 = mn0; mr1 = mn1;

        float rs0 = 0.0f, rs1 = 0.0f;
#pragma unroll
        for (int nt = 0; nt < 8; nt++) {
            s[nt][0] = ex2(s[nt][0] - mn0);
            s[nt][1] = ex2(s[nt][1] - mn0);
            s[nt][2] = ex2(s[nt][2] - mn1);
            s[nt][3] = ex2(s[nt][3] - mn1);
            rs0 += s[nt][0] + s[nt][1];
            rs1 += s[nt][2] + s[nt][3];
        }
        rs0 += __shfl_xor_sync(0xffffffffu, rs0, 1);
        rs0 += __shfl_xor_sync(0xffffffffu, rs0, 2);
        rs1 += __shfl_xor_sync(0xffffffffu, rs1, 1);
        rs1 += __shfl_xor_sync(0xffffffffu, rs1, 2);
        lr0 = lr0 * al0 + rs0;
        lr1 = lr1 * al1 + rs1;
#pragma unroll
        for (int nt = 0; nt < 8; nt++) {
            O[nt][0] *= al0; O[nt][1] *= al0;
            O[nt][2] *= al1; O[nt][3] *= al1;
        }

        // ---- O += P @ V: convert P per-ks (transient regs), then MMA ----
#pragma unroll
        for (int ks = 0; ks < 4; ks++) {
            // build this k-chunk's A-frag from s[2ks], s[2ks+1]
            uint32_t ph[4], pl[4];
            {
                int t0 = 2 * ks, t1 = 2 * ks + 1;
                __nv_bfloat16 ha, la, hb, lb;
                fsplit(s[t0][0], ha, la); fsplit(s[t0][1], hb, lb);
                ph[0] = pack2(ha, hb); pl[0] = pack2(la, lb);
                fsplit(s[t0][2], ha, la); fsplit(s[t0][3], hb, lb);
                ph[1] = pack2(ha, hb); pl[1] = pack2(la, lb);
                fsplit(s[t1][0], ha, la); fsplit(s[t1][1], hb, lb);
                ph[2] = pack2(ha, hb); pl[2] = pack2(la, lb);
                fsplit(s[t1][2], ha, la); fsplit(s[t1][3], hb, lb);
                ph[3] = pack2(ha, hb); pl[3] = pack2(la, lb);
            }
            uint32_t vh[16], vl[16];
#pragma unroll
            for (int p = 0; p < 4; p++) {
                ldsm4(&vh[p * 4], vbH + (uint32_t)((p * 16 * AST + ks * 16) * 2) + laneB);
                ldsm4(&vl[p * 4], vbL + (uint32_t)((p * 16 * AST + ks * 16) * 2) + laneB);
            }
#pragma unroll
            for (int nt = 0; nt < 8; nt++) {
                const uint32_t* vph = &vh[(nt >> 1) * 4 + (nt & 1) * 2];
                const uint32_t* vpl = &vl[(nt >> 1) * 4 + (nt & 1) * 2];
                mma_bf16(O[nt], ph, vph);
                mma_bf16(O[nt], pl, vph);
                mma_bf16(O[nt], ph, vpl);
            }
        }
        __syncthreads();
    }

    // ---- epilogue: unnormalized partials ----
    int r0 = w * 16 + (lane >> 2);
#pragma unroll
    for (int nt = 0; nt < 8; nt++) {
        int c = nt * 8 + (lane & 3) * 2;
        *(float2*)(&g_pO[part][r0][c])     = make_float2(O[nt][0], O[nt][1]);
        *(float2*)(&g_pO[part][r0 + 8][c]) = make_float2(O[nt][2], O[nt][3]);
    }
    if ((lane & 3) == 0) {
        g_pm[part][r0] = mr0;     g_pl[part][r0] = lr0;
        g_pm[part][r0 + 8] = mr1; g_pl[part][r0 + 8] = lr1;
    }
}

// =================================================================
// Kernel 4: combine. 1024 blocks x 256 thr; thread = one float4 pair.
// =================================================================
__global__ __launch_bounds__(256) void combine(float* __restrict__ out)
{
    const int pair  = blockIdx.x >> 3;           // b*16 + qt
    const int chunk = blockIdx.x & 7;
    const int r = chunk * 16 + (threadIdx.x >> 4);
    const int c = (threadIdx.x & 15) * 4;
    const int p0 = pair * 2, p1 = p0 + 1;

    float m0 = g_pm[p0][r], l0 = g_pl[p0][r];
    float m1 = g_pm[p1][r], l1 = g_pl[p1][r];
    float M  = fmaxf(m0, m1);
    float w0 = ex2(m0 - M), w1 = ex2(m1 - M);
    float inv = 1.0f / (w0 * l0 + w1 * l1);
    float c0 = w0 * inv, c1 = w1 * inv;

    const int b = pair >> 4, qt = pair & 15;
    float4 a = *(const float4*)(&g_pO[p0][r][c]);
    float4 d = *(const float4*)(&g_pO[p1][r][c]);
    float* op = out + ((size_t)b * SEQ + qt * 128 + r) * HS + c;
    *(float4*)op = make_float4(a.x * c0 + d.x * c1, a.y * c0 + d.y * c1,
                               a.z * c0 + d.z * c1, a.w * c0 + d.w * c1);
}

// =================================================================
extern "C" void kernel_launch(void* const* d_in, const int* in_sizes, int n_in,
                              void* d_out, int out_size)
{
    (void)in_sizes; (void)n_in; (void)out_size;
    const float* query = (const float*)d_in[0];
    const float* key   = (const float*)d_in[1];
    const float* value = (const float*)d_in[2];
    const float* Wq    = (const float*)d_in[3];
    const float* Wk    = (const float*)d_in[4];
    const float* Wv    = (const float*)d_in[5];

    prep_w<<<dim3(256, 3, 1), 256>>>(Wq, Wk, Wv);

    proj_mma<<<dim3(128, 3, 1), 256>>>(query, key, value);

    cudaFuncSetAttribute(attn_mma, cudaFuncAttributeMaxDynamicSharedMemorySize, ATTN_SMEM);
    attn_mma<<<dim3(32, NB, 1), 256, ATTN_SMEM>>>();

    combine<<<NB * 16 * 8, 256>>>((float*)d_out);
}

// round 10
// speedup vs baseline: 1.0762x; 1.0681x over previous
#include <cuda_runtime.h>
#include <cuda_bf16.h>
#include <cstdint>

#define NB   8
#define SEQ  2048
#define DIM  1024
#define HS   64

// ---------------- device scratch (no cudaMalloc allowed) ----------------
__device__ __nv_bfloat16 g_qh [NB * SEQ * HS];   // q*(0.125*log2e) hi, [b][s][h]
__device__ __nv_bfloat16 g_ql [NB * SEQ * HS];
__device__ __nv_bfloat16 g_kh [NB * SEQ * HS];   // k hi, [b][s][h]
__device__ __nv_bfloat16 g_kl [NB * SEQ * HS];
__device__ __nv_bfloat16 g_vth[NB * HS * SEQ];   // v^T hi: [b][h][s]
__device__ __nv_bfloat16 g_vtl[NB * HS * SEQ];
__device__ __nv_bfloat16 g_wth[3 * HS * DIM];    // W^T hi: [mode][n][k]
__device__ __nv_bfloat16 g_wtl[3 * HS * DIM];

// split-KV partials: 2 halves per (b, qtile)
#define NPART (NB * 16 * 2)
__device__ float g_pO[NPART][128][64];           // unnormalized partial O
__device__ float g_pm[NPART][128];               // row max (log2 domain)
__device__ float g_pl[NPART][128];               // row sum

// ---------------- helpers ----------------
__device__ __forceinline__ uint32_t s2u(const void* p) {
    uint32_t a;
    asm("{ .reg .u64 t; cvta.to.shared.u64 t, %1; cvt.u32.u64 %0, t; }" : "=r"(a) : "l"(p));
    return a;
}
__device__ __forceinline__ void fsplit(float a, __nv_bfloat16& h, __nv_bfloat16& l) {
    h = __float2bfloat16(a);
    l = __float2bfloat16(a - __bfloat162float(h));
}
__device__ __forceinline__ uint32_t pack2(__nv_bfloat16 a, __nv_bfloat16 b) {
    __nv_bfloat162 v = __halves2bfloat162(a, b);
    return *reinterpret_cast<uint32_t*>(&v);
}
__device__ __forceinline__ float ex2(float x) {
    float y;
    asm("ex2.approx.f32 %0, %1;" : "=f"(y) : "f"(x));
    return y;
}
__device__ __forceinline__ void ldsm4(uint32_t r[4], uint32_t addr) {
    asm volatile("ldmatrix.sync.aligned.m8n8.x4.shared.b16 {%0,%1,%2,%3}, [%4];"
                 : "=r"(r[0]), "=r"(r[1]), "=r"(r[2]), "=r"(r[3]) : "r"(addr));
}
__device__ __forceinline__ void mma_bf16(float d[4], const uint32_t a[4], const uint32_t b[2]) {
    asm volatile("mma.sync.aligned.m16n8k16.row.col.f32.bf16.bf16.f32 "
                 "{%0,%1,%2,%3},{%4,%5,%6,%7},{%8,%9},{%0,%1,%2,%3};"
                 : "+f"(d[0]), "+f"(d[1]), "+f"(d[2]), "+f"(d[3])
                 : "r"(a[0]), "r"(a[1]), "r"(a[2]), "r"(a[3]), "r"(b[0]), "r"(b[1]));
}
__device__ __forceinline__ void cpa16(uint32_t saddr, const void* gaddr) {
    asm volatile("cp.async.cg.shared.global [%0], [%1], 16;" :: "r"(saddr), "l"(gaddr));
}
#define CP_COMMIT() asm volatile("cp.async.commit_group;" ::: "memory")
#define CP_WAIT3()  asm volatile("cp.async.wait_group 3;" ::: "memory")
#define CP_WAIT2()  asm volatile("cp.async.wait_group 2;" ::: "memory")
#define CP_WAIT1()  asm volatile("cp.async.wait_group 1;" ::: "memory")
#define CP_WAIT0()  asm volatile("cp.async.wait_group 0;" ::: "memory")

// =================================================================
// Kernel 1: W -> W^T bf16 hi/lo. Wq pre-scaled by 0.125*log2(e).
// =================================================================
__global__ void prep_w(const float* __restrict__ Wq, const float* __restrict__ Wk,
                       const float* __restrict__ Wv)
{
    int mode = blockIdx.y;
    const float* W = (mode == 0) ? Wq : ((mode == 1) ? Wk : Wv);
    float sc = (mode == 0) ? 0.18033688011112042f : 1.0f;   // 0.125 * log2(e)
    int t = blockIdx.x * 256 + threadIdx.x;      // 0..65535
    int k = t & 1023, n = t >> 10;
    float x = W[(size_t)k * HS + n] * sc;
    __nv_bfloat16 h, l;
    fsplit(x, h, l);
    g_wth[((size_t)mode * HS + n) * DIM + k] = h;
    g_wtl[((size_t)mode * HS + n) * DIM + k] = l;
}

// =================================================================
// Kernel 2: projections via mma.sync bf16-split, 2 blocks/SM.
// =================================================================
#define PST 40

__global__ __launch_bounds__(256, 2) void proj_mma(
    const float* __restrict__ Xq, const float* __restrict__ Xk, const float* __restrict__ Xv)
{
    __shared__ __align__(16) __nv_bfloat16 sAh[128 * PST];
    __shared__ __align__(16) __nv_bfloat16 sAl[128 * PST];
    __shared__ __align__(16) __nv_bfloat16 sBh[64 * PST];
    __shared__ __align__(16) __nv_bfloat16 sBl[64 * PST];

    const int tid = threadIdx.x;
    const int lane = tid & 31, w = tid >> 5;
    const int mode = blockIdx.y;
    const int row0 = blockIdx.x * 128;

    const float* X = (mode == 0) ? Xq : ((mode == 1) ? Xk : Xv);
    const __nv_bfloat16* WTh = g_wth + (size_t)mode * HS * DIM;
    const __nv_bfloat16* WTl = g_wtl + (size_t)mode * HS * DIM;

    const uint32_t aBase = s2u(sAh), alBase = s2u(sAl);
    const uint32_t bBase = s2u(sBh), blBase = s2u(sBl);
    const uint32_t laneA = (uint32_t)((((lane & 7) + (((lane >> 3) & 1) << 3)) * PST + ((lane >> 4) << 3)) * 2);
    const uint32_t laneB = (uint32_t)((((lane & 7) + ((lane >> 4) << 3)) * PST + (((lane >> 3) & 1) << 3)) * 2);

    float acc[8][4];
#pragma unroll
    for (int nt = 0; nt < 8; nt++)
#pragma unroll
        for (int e = 0; e < 4; e++) acc[nt][e] = 0.0f;

    float4 fa[4];
    uint4 wbh, wbl;
    const int bn = tid >> 2, bq = tid & 3;

#pragma unroll
    for (int it = 0; it < 4; it++) {
        int idx = tid + it * 256, m = idx >> 3, kq = idx & 7;
        fa[it] = *(const float4*)(X + (size_t)(row0 + m) * DIM + kq * 4);
    }
    wbh = *(const uint4*)(WTh + (size_t)bn * DIM + bq * 8);
    wbl = *(const uint4*)(WTl + (size_t)bn * DIM + bq * 8);

    for (int kb = 0; kb < 32; kb++) {
#pragma unroll
        for (int it = 0; it < 4; it++) {
            int idx = tid + it * 256, m = idx >> 3, kq = idx & 7;
            __nv_bfloat16 h0, h1, h2, h3, l0, l1, l2, l3;
            fsplit(fa[it].x, h0, l0); fsplit(fa[it].y, h1, l1);
            fsplit(fa[it].z, h2, l2); fsplit(fa[it].w, h3, l3);
            *(uint2*)(sAh + m * PST + kq * 4) = make_uint2(pack2(h0, h1), pack2(h2, h3));
            *(uint2*)(sAl + m * PST + kq * 4) = make_uint2(pack2(l0, l1), pack2(l2, l3));
        }
        *(uint4*)(sBh + bn * PST + bq * 8) = wbh;
        *(uint4*)(sBl + bn * PST + bq * 8) = wbl;
        __syncthreads();

        if (kb + 1 < 32) {
            int kc = (kb + 1) * 32;
#pragma unroll
            for (int it = 0; it < 4; it++) {
                int idx = tid + it * 256, m = idx >> 3, kq = idx & 7;
                fa[it] = *(const float4*)(X + (size_t)(row0 + m) * DIM + kc + kq * 4);
            }
            wbh = *(const uint4*)(WTh + (size_t)bn * DIM + kc + bq * 8);
            wbl = *(const uint4*)(WTl + (size_t)bn * DIM + kc + bq * 8);
        }

#pragma unroll
        for (int ks = 0; ks < 2; ks++) {
            uint32_t ah[4], al_[4];
            ldsm4(ah,  aBase  + (uint32_t)((w * 16 * PST + ks * 16) * 2) + laneA);
            ldsm4(al_, alBase + (uint32_t)((w * 16 * PST + ks * 16) * 2) + laneA);
            uint32_t bh[16], bl[16];
#pragma unroll
            for (int p = 0; p < 4; p++) {
                ldsm4(&bh[p * 4], bBase  + (uint32_t)((p * 16 * PST + ks * 16) * 2) + laneB);
                ldsm4(&bl[p * 4], blBase + (uint32_t)((p * 16 * PST + ks * 16) * 2) + laneB);
            }
#pragma unroll
            for (int nt = 0; nt < 8; nt++) {
                const uint32_t* bph = &bh[(nt >> 1) * 4 + (nt & 1) * 2];
                const uint32_t* bpl = &bl[(nt >> 1) * 4 + (nt & 1) * 2];
                mma_bf16(acc[nt], ah, bph);
                mma_bf16(acc[nt], ah, bpl);
                mma_bf16(acc[nt], al_, bph);
            }
        }
        __syncthreads();
    }

    const int rl = row0 + w * 16 + (lane >> 2);
    if (mode == 2) {
        const int b = rl / SEQ, s = rl % SEQ;
#pragma unroll
        for (int nt = 0; nt < 8; nt++) {
            int c = nt * 8 + (lane & 3) * 2;
#pragma unroll
            for (int e = 0; e < 2; e++) {
                __nv_bfloat16 h, l;
                fsplit(acc[nt][e], h, l);
                g_vth[((size_t)b * HS + c + e) * SEQ + s] = h;
                g_vtl[((size_t)b * HS + c + e) * SEQ + s] = l;
                fsplit(acc[nt][2 + e], h, l);
                g_vth[((size_t)b * HS + c + e) * SEQ + s + 8] = h;
                g_vtl[((size_t)b * HS + c + e) * SEQ + s + 8] = l;
            }
        }
    } else {
        __nv_bfloat16* Oh = mode ? g_kh : g_qh;
        __nv_bfloat16* Ol = mode ? g_kl : g_ql;
#pragma unroll
        for (int nt = 0; nt < 8; nt++) {
            int c = nt * 8 + (lane & 3) * 2;
            __nv_bfloat16 h0, l0, h1, l1;
            fsplit(acc[nt][0], h0, l0); fsplit(acc[nt][1], h1, l1);
            *(uint32_t*)(Oh + (size_t)rl * HS + c) = pack2(h0, h1);
            *(uint32_t*)(Ol + (size_t)rl * HS + c) = pack2(l0, l1);
            fsplit(acc[nt][2], h0, l0); fsplit(acc[nt][3], h1, l1);
            *(uint32_t*)(Oh + (size_t)(rl + 8) * HS + c) = pack2(h0, h1);
            *(uint32_t*)(Ol + (size_t)(rl + 8) * HS + c) = pack2(l0, l1);
        }
    }
}

// =================================================================
// Kernel 3: split-KV causal flash attention. Occupancy 1 (uncapped
// regs, persistent Q frags). 4 KV buffers, cp.async issued 3 tiles
// ahead (wait_group 2 -> sync -> issue kt+3 -> compute kt).
// =================================================================
#define AST 72
#define OFF_QH 0
#define OFF_QL 18432
#define OFF_BUF 36864
#define BUF_STRIDE 36864
#define ARR_STRIDE 9216
#define ATTN_SMEM (36864 + 4 * 36864)

__global__ __launch_bounds__(256, 1) void attn_mma()
{
    extern __shared__ __align__(16) char sm[];
    const uint32_t sb = s2u(sm);
    const int tid = threadIdx.x, lane = tid & 31, w = tid >> 5;
    const int b = blockIdx.y;
    const int qt   = 15 - ((int)blockIdx.x >> 1);
    const int half = (int)blockIdx.x & 1;
    const int k0 = half ? (qt + 1) : 0;
    const int k1 = half ? (2 * qt + 2) : (qt + 1);
    const int part = ((b * 16 + qt) * 2) + half;

    const __nv_bfloat16* Qh  = g_qh + ((size_t)b * SEQ + qt * 128) * HS;
    const __nv_bfloat16* Ql  = g_ql + ((size_t)b * SEQ + qt * 128) * HS;
    const __nv_bfloat16* Kh0 = g_kh + (size_t)b * SEQ * HS;
    const __nv_bfloat16* Kl0 = g_kl + (size_t)b * SEQ * HS;
    const __nv_bfloat16* Vh0 = g_vth + (size_t)b * HS * SEQ;
    const __nv_bfloat16* Vl0 = g_vtl + (size_t)b * HS * SEQ;

    // group 0: Q tile
#pragma unroll
    for (int it = 0; it < 4; it++) {
        int idx = tid + it * 256, r = idx >> 3, q = idx & 7;
        cpa16(sb + OFF_QH + (r * AST + q * 8) * 2, Qh + (size_t)r * HS + q * 8);
        cpa16(sb + OFF_QL + (r * AST + q * 8) * 2, Ql + (size_t)r * HS + q * 8);
    }
    CP_COMMIT();

    // guarded issue: always commits a group (possibly empty) to keep counts aligned
    auto issue_kv = [&](int kt) {
        if (kt < k1) {
            uint32_t base = sb + OFF_BUF + ((kt - k0) & 3) * BUF_STRIDE;
#pragma unroll
            for (int it = 0; it < 8; it++) {
                int idx = tid + it * 256;
                int a = idx >> 9, rem = idx & 511;
                int r = rem >> 3, q = rem & 7;
                const __nv_bfloat16* src;
                if (a == 0)      src = Kh0 + (size_t)(kt * 64 + r) * HS + q * 8;
                else if (a == 1) src = Kl0 + (size_t)(kt * 64 + r) * HS + q * 8;
                else if (a == 2) src = Vh0 + (size_t)r * SEQ + kt * 64 + q * 8;
                else             src = Vl0 + (size_t)r * SEQ + kt * 64 + q * 8;
                cpa16(base + a * ARR_STRIDE + (r * AST + q * 8) * 2, src);
            }
        }
        CP_COMMIT();
    };
    issue_kv(k0);          // group 1
    issue_kv(k0 + 1);      // group 2
    issue_kv(k0 + 2);      // group 3

    CP_WAIT3();            // Q (group 0) complete
    __syncthreads();

    const uint32_t laneA = (uint32_t)((((lane & 7) + (((lane >> 3) & 1) << 3)) * AST + ((lane >> 4) << 3)) * 2);
    const uint32_t laneB = (uint32_t)((((lane & 7) + ((lane >> 4) << 3)) * AST + (((lane >> 3) & 1) << 3)) * 2);

    // persistent Q fragments (occ 1: registers are plentiful)
    uint32_t qh[4][4], ql[4][4];
#pragma unroll
    for (int ks = 0; ks < 4; ks++) {
        ldsm4(qh[ks], sb + OFF_QH + (uint32_t)((w * 16 * AST + ks * 16) * 2) + laneA);
        ldsm4(ql[ks], sb + OFF_QL + (uint32_t)((w * 16 * AST + ks * 16) * 2) + laneA);
    }

    float O[8][4];
#pragma unroll
    for (int nt = 0; nt < 8; nt++)
#pragma unroll
        for (int e = 0; e < 4; e++) O[nt][e] = 0.0f;
    float mr0 = -1e30f, mr1 = -1e30f, lr0 = 0.0f, lr1 = 0.0f;

    for (int kt = k0; kt < k1; kt++) {
        const int bf = (kt - k0) & 3;

        CP_WAIT2();              // tile kt complete (<=2 newer groups outstanding)
        __syncthreads();         // tile kt visible; all warps done with tile kt-1
        issue_kv(kt + 3);        // refill the buffer freed by tile kt-1

        // fully-masked warp-tiles (final diagonal tile, warps 0-3): skip compute
        if (kt * 64 <= qt * 128 + w * 16 + 15) {

        const uint32_t kbH = sb + OFF_BUF + bf * BUF_STRIDE;
        const uint32_t kbL = kbH + ARR_STRIDE;
        const uint32_t vbH = kbH + 2 * ARR_STRIDE;
        const uint32_t vbL = kbH + 3 * ARR_STRIDE;

        // ---- S = Q K^T (hh + hl + lh) ----
        float s[8][4];
#pragma unroll
        for (int nt = 0; nt < 8; nt++)
#pragma unroll
            for (int e = 0; e < 4; e++) s[nt][e] = 0.0f;

#pragma unroll
        for (int ks = 0; ks < 4; ks++) {
            uint32_t bh[16], bl[16];
#pragma unroll
            for (int p = 0; p < 4; p++) {
                ldsm4(&bh[p * 4], kbH + (uint32_t)((p * 16 * AST + ks * 16) * 2) + laneB);
                ldsm4(&bl[p * 4], kbL + (uint32_t)((p * 16 * AST + ks * 16) * 2) + laneB);
            }
#pragma unroll
            for (int nt = 0; nt < 8; nt++) {
                const uint32_t* bph = &bh[(nt >> 1) * 4 + (nt & 1) * 2];
                const uint32_t* bpl = &bl[(nt >> 1) * 4 + (nt & 1) * 2];
                mma_bf16(s[nt], qh[ks], bph);
                mma_bf16(s[nt], qh[ks], bpl);
                mma_bf16(s[nt], ql[ks], bph);
            }
        }

        // ---- causal mask (diagonal tiles only) ----
        if (kt >= 2 * qt) {
            int lim = qt * 128 + w * 16 + (lane >> 2) - kt * 64;
#pragma unroll
            for (int nt = 0; nt < 8; nt++) {
                int c = nt * 8 + (lane & 3) * 2;
                if (c     > lim)     s[nt][0] = -1e30f;
                if (c + 1 > lim)     s[nt][1] = -1e30f;
                if (c     > lim + 8) s[nt][2] = -1e30f;
                if (c + 1 > lim + 8) s[nt][3] = -1e30f;
            }
        }

        // ---- online softmax (exp2 domain) ----
        float rm0 = -1e30f, rm1 = -1e30f;
#pragma unroll
        for (int nt = 0; nt < 8; nt++) {
            rm0 = fmaxf(rm0, fmaxf(s[nt][0], s[nt][1]));
            rm1 = fmaxf(rm1, fmaxf(s[nt][2], s[nt][3]));
        }
        rm0 = fmaxf(rm0, __shfl_xor_sync(0xffffffffu, rm0, 1));
        rm0 = fmaxf(rm0, __shfl_xor_sync(0xffffffffu, rm0, 2));
        rm1 = fmaxf(rm1, __shfl_xor_sync(0xffffffffu, rm1, 1));
        rm1 = fmaxf(rm1, __shfl_xor_sync(0xffffffffu, rm1, 2));
        float mn0 = fmaxf(mr0, rm0), mn1 = fmaxf(mr1, rm1);
        float al0 = ex2(mr0 - mn0), al1 = ex2(mr1 - mn1);
        mr0 = mn0; mr1 = mn1;

        float rs0 = 0.0f, rs1 = 0.0f;
#pragma unroll
        for (int nt = 0; nt < 8; nt++) {
            s[nt][0] = ex2(s[nt][0] - mn0);
            s[nt][1] = ex2(s[nt][1] - mn0);
            s[nt][2] = ex2(s[nt][2] - mn1);
            s[nt][3] = ex2(s[nt][3] - mn1);
            rs0 += s[nt][0] + s[nt][1];
            rs1 += s[nt][2] + s[nt][3];
        }
        rs0 += __shfl_xor_sync(0xffffffffu, rs0, 1);
        rs0 += __shfl_xor_sync(0xffffffffu, rs0, 2);
        rs1 += __shfl_xor_sync(0xffffffffu, rs1, 1);
        rs1 += __shfl_xor_sync(0xffffffffu, rs1, 2);
        lr0 = lr0 * al0 + rs0;
        lr1 = lr1 * al1 + rs1;
#pragma unroll
        for (int nt = 0; nt < 8; nt++) {
            O[nt][0] *= al0; O[nt][1] *= al0;
            O[nt][2] *= al1; O[nt][3] *= al1;
        }

        // ---- O += P @ V: convert P per-ks (transient regs), then MMA ----
#pragma unroll
        for (int ks = 0; ks < 4; ks++) {
            uint32_t ph[4], pl[4];
            {
                int t0 = 2 * ks, t1 = 2 * ks + 1;
                __nv_bfloat16 ha, la, hb, lb;
                fsplit(s[t0][0], ha, la); fsplit(s[t0][1], hb, lb);
                ph[0] = pack2(ha, hb); pl[0] = pack2(la, lb);
                fsplit(s[t0][2], ha, la); fsplit(s[t0][3], hb, lb);
                ph[1] = pack2(ha, hb); pl[1] = pack2(la, lb);
                fsplit(s[t1][0], ha, la); fsplit(s[t1][1], hb, lb);
                ph[2] = pack2(ha, hb); pl[2] = pack2(la, lb);
                fsplit(s[t1][2], ha, la); fsplit(s[t1][3], hb, lb);
                ph[3] = pack2(ha, hb); pl[3] = pack2(la, lb);
            }
            uint32_t vh[16], vl[16];
#pragma unroll
            for (int p = 0; p < 4; p++) {
                ldsm4(&vh[p * 4], vbH + (uint32_t)((p * 16 * AST + ks * 16) * 2) + laneB);
                ldsm4(&vl[p * 4], vbL + (uint32_t)((p * 16 * AST + ks * 16) * 2) + laneB);
            }
#pragma unroll
            for (int nt = 0; nt < 8; nt++) {
                const uint32_t* vph = &vh[(nt >> 1) * 4 + (nt & 1) * 2];
                const uint32_t* vpl = &vl[(nt >> 1) * 4 + (nt & 1) * 2];
                mma_bf16(O[nt], ph, vph);
                mma_bf16(O[nt], pl, vph);
                mma_bf16(O[nt], ph, vpl);
            }
        }

        } // end skip-fully-masked
    }

    // ---- epilogue: unnormalized partials ----
    int r0 = w * 16 + (lane >> 2);
#pragma unroll
    for (int nt = 0; nt < 8; nt++) {
        int c = nt * 8 + (lane & 3) * 2;
        *(float2*)(&g_pO[part][r0][c])     = make_float2(O[nt][0], O[nt][1]);
        *(float2*)(&g_pO[part][r0 + 8][c]) = make_float2(O[nt][2], O[nt][3]);
    }
    if ((lane & 3) == 0) {
        g_pm[part][r0] = mr0;     g_pl[part][r0] = lr0;
        g_pm[part][r0 + 8] = mr1; g_pl[part][r0 + 8] = lr1;
    }
}

// =================================================================
// Kernel 4: combine. 1024 blocks x 256 thr; thread = one float4.
// =================================================================
__global__ __launch_bounds__(256) void combine(float* __restrict__ out)
{
    const int pair  = blockIdx.x >> 3;           // b*16 + qt
    const int chunk = blockIdx.x & 7;
    const int r = chunk * 16 + (threadIdx.x >> 4);
    const int c = (threadIdx.x & 15) * 4;
    const int p0 = pair * 2, p1 = p0 + 1;

    float m0 = g_pm[p0][r], l0 = g_pl[p0][r];
    float m1 = g_pm[p1][r], l1 = g_pl[p1][r];
    float M  = fmaxf(m0, m1);
    float w0 = ex2(m0 - M), w1 = ex2(m1 - M);
    float inv = 1.0f / (w0 * l0 + w1 * l1);
    float c0 = w0 * inv, c1 = w1 * inv;

    const int b = pair >> 4, qt = pair & 15;
    float4 a = *(const float4*)(&g_pO[p0][r][c]);
    float4 d = *(const float4*)(&g_pO[p1][r][c]);
    float* op = out + ((size_t)b * SEQ + qt * 128 + r) * HS + c;
    *(float4*)op = make_float4(a.x * c0 + d.x * c1, a.y * c0 + d.y * c1,
                               a.z * c0 + d.z * c1, a.w * c0 + d.w * c1);
}

// =================================================================
extern "C" void kernel_launch(void* const* d_in, const int* in_sizes, int n_in,
                              void* d_out, int out_size)
{
    (void)in_sizes; (void)n_in; (void)out_size;
    const float* query = (const float*)d_in[0];
    const float* key   = (const float*)d_in[1];
    const float* value = (const float*)d_in[2];
    const float* Wq    = (const float*)d_in[3];
    const float* Wk    = (const float*)d_in[4];
    const float* Wv    = (const float*)d_in[5];

    prep_w<<<dim3(256, 3, 1), 256>>>(Wq, Wk, Wv);

    proj_mma<<<dim3(128, 3, 1), 256>>>(query, key, value);

    cudaFuncSetAttribute(attn_mma, cudaFuncAttributeMaxDynamicSharedMemorySize, ATTN_SMEM);
    attn_mma<<<dim3(32, NB, 1), 256, ATTN_SMEM>>>();

    combine<<<NB * 16 * 8, 256>>>((float*)d_out);
}

// round 11
// speedup vs baseline: 1.3214x; 1.2279x over previous
#include <cuda_runtime.h>
#include <cuda_fp16.h>
#include <cstdint>

#define NB   8
#define SEQ  2048
#define DIM  1024
#define HS   64

// ---------------- device scratch (no cudaMalloc allowed) ----------------
__device__ __half g_q  [NB * SEQ * HS];   // q*(0.125*log2e), fp16 single, [b][s][h]
__device__ __half g_kh [NB * SEQ * HS];   // k hi, [b][s][h]
__device__ __half g_kl [NB * SEQ * HS];   // k lo
__device__ __half g_vt [NB * HS * SEQ];   // v^T fp16 single: [b][h][s]
__device__ __half g_wth[3 * HS * DIM];    // W^T hi: [mode][n][k]
__device__ __half g_wtl[3 * HS * DIM];    // W^T lo

// split-KV partials: 2 halves per (b, qtile)
#define NPART (NB * 16 * 2)
__device__ float g_pO[NPART][128][64];
__device__ float g_pm[NPART][128];
__device__ float g_pl[NPART][128];

// ---------------- helpers ----------------
__device__ __forceinline__ uint32_t s2u(const void* p) {
    uint32_t a;
    asm("{ .reg .u64 t; cvta.to.shared.u64 t, %1; cvt.u32.u64 %0, t; }" : "=r"(a) : "l"(p));
    return a;
}
__device__ __forceinline__ void fsplith(float a, __half& h, __half& l) {
    h = __float2half_rn(a);
    l = __float2half_rn(a - __half2float(h));
}
__device__ __forceinline__ uint32_t packh2(__half a, __half b) {
    __half2 v = __halves2half2(a, b);
    return *reinterpret_cast<uint32_t*>(&v);
}
__device__ __forceinline__ float ex2(float x) {
    float y;
    asm("ex2.approx.f32 %0, %1;" : "=f"(y) : "f"(x));
    return y;
}
__device__ __forceinline__ void ldsm4(uint32_t r[4], uint32_t addr) {
    asm volatile("ldmatrix.sync.aligned.m8n8.x4.shared.b16 {%0,%1,%2,%3}, [%4];"
                 : "=r"(r[0]), "=r"(r[1]), "=r"(r[2]), "=r"(r[3]) : "r"(addr));
}
__device__ __forceinline__ void mma_f16(float d[4], const uint32_t a[4], const uint32_t b[2]) {
    asm volatile("mma.sync.aligned.m16n8k16.row.col.f32.f16.f16.f32 "
                 "{%0,%1,%2,%3},{%4,%5,%6,%7},{%8,%9},{%0,%1,%2,%3};"
                 : "+f"(d[0]), "+f"(d[1]), "+f"(d[2]), "+f"(d[3])
                 : "r"(a[0]), "r"(a[1]), "r"(a[2]), "r"(a[3]), "r"(b[0]), "r"(b[1]));
}
__device__ __forceinline__ void cpa16(uint32_t saddr, const void* gaddr) {
    asm volatile("cp.async.cg.shared.global [%0], [%1], 16;" :: "r"(saddr), "l"(gaddr));
}
#define CP_COMMIT() asm volatile("cp.async.commit_group;" ::: "memory")
#define CP_WAIT3()  asm volatile("cp.async.wait_group 3;" ::: "memory")
#define CP_WAIT2()  asm volatile("cp.async.wait_group 2;" ::: "memory")

// =================================================================
// Kernel 1: W -> W^T fp16 hi/lo. Wq pre-scaled by 0.125*log2(e).
// =================================================================
__global__ void prep_w(const float* __restrict__ Wq, const float* __restrict__ Wk,
                       const float* __restrict__ Wv)
{
    int mode = blockIdx.y;
    const float* W = (mode == 0) ? Wq : ((mode == 1) ? Wk : Wv);
    float sc = (mode == 0) ? 0.18033688011112042f : 1.0f;   // 0.125 * log2(e)
    int t = blockIdx.x * 256 + threadIdx.x;      // 0..65535
    int k = t & 1023, n = t >> 10;
    float x = W[(size_t)k * HS + n] * sc;
    __half h, l;
    fsplith(x, h, l);
    g_wth[((size_t)mode * HS + n) * DIM + k] = h;
    g_wtl[((size_t)mode * HS + n) * DIM + k] = l;
}

// =================================================================
// Kernel 2: projections, fp16 2-product: C = Xh*(Wh + Wl).
// =================================================================
#define PST 40

__global__ __launch_bounds__(256, 2) void proj_mma(
    const float* __restrict__ Xq, const float* __restrict__ Xk, const float* __restrict__ Xv)
{
    __shared__ __align__(16) __half sA [128 * PST];
    __shared__ __align__(16) __half sBh[64 * PST];
    __shared__ __align__(16) __half sBl[64 * PST];

    const int tid = threadIdx.x;
    const int lane = tid & 31, w = tid >> 5;
    const int mode = blockIdx.y;
    const int row0 = blockIdx.x * 128;

    const float* X = (mode == 0) ? Xq : ((mode == 1) ? Xk : Xv);
    const __half* WTh = g_wth + (size_t)mode * HS * DIM;
    const __half* WTl = g_wtl + (size_t)mode * HS * DIM;

    const uint32_t aBase = s2u(sA);
    const uint32_t bBase = s2u(sBh), blBase = s2u(sBl);
    const uint32_t laneA = (uint32_t)((((lane & 7) + (((lane >> 3) & 1) << 3)) * PST + ((lane >> 4) << 3)) * 2);
    const uint32_t laneB = (uint32_t)((((lane & 7) + ((lane >> 4) << 3)) * PST + (((lane >> 3) & 1) << 3)) * 2);

    float acc[8][4];
#pragma unroll
    for (int nt = 0; nt < 8; nt++)
#pragma unroll
        for (int e = 0; e < 4; e++) acc[nt][e] = 0.0f;

    float4 fa[4];
    uint4 wbh, wbl;
    const int bn = tid >> 2, bq = tid & 3;

#pragma unroll
    for (int it = 0; it < 4; it++) {
        int idx = tid + it * 256, m = idx >> 3, kq = idx & 7;
        fa[it] = *(const float4*)(X + (size_t)(row0 + m) * DIM + kq * 4);
    }
    wbh = *(const uint4*)(WTh + (size_t)bn * DIM + bq * 8);
    wbl = *(const uint4*)(WTl + (size_t)bn * DIM + bq * 8);

    for (int kb = 0; kb < 32; kb++) {
#pragma unroll
        for (int it = 0; it < 4; it++) {
            int idx = tid + it * 256, m = idx >> 3, kq = idx & 7;
            *(uint2*)(sA + m * PST + kq * 4) = make_uint2(
                packh2(__float2half_rn(fa[it].x), __float2half_rn(fa[it].y)),
                packh2(__float2half_rn(fa[it].z), __float2half_rn(fa[it].w)));
        }
        *(uint4*)(sBh + bn * PST + bq * 8) = wbh;
        *(uint4*)(sBl + bn * PST + bq * 8) = wbl;
        __syncthreads();

        if (kb + 1 < 32) {
            int kc = (kb + 1) * 32;
#pragma unroll
            for (int it = 0; it < 4; it++) {
                int idx = tid + it * 256, m = idx >> 3, kq = idx & 7;
                fa[it] = *(const float4*)(X + (size_t)(row0 + m) * DIM + kc + kq * 4);
            }
            wbh = *(const uint4*)(WTh + (size_t)bn * DIM + kc + bq * 8);
            wbl = *(const uint4*)(WTl + (size_t)bn * DIM + kc + bq * 8);
        }

#pragma unroll
        for (int ks = 0; ks < 2; ks++) {
            uint32_t ah[4];
            ldsm4(ah, aBase + (uint32_t)((w * 16 * PST + ks * 16) * 2) + laneA);
            uint32_t bh[16], bl[16];
#pragma unroll
            for (int p = 0; p < 4; p++) {
                ldsm4(&bh[p * 4], bBase  + (uint32_t)((p * 16 * PST + ks * 16) * 2) + laneB);
                ldsm4(&bl[p * 4], blBase + (uint32_t)((p * 16 * PST + ks * 16) * 2) + laneB);
            }
#pragma unroll
            for (int nt = 0; nt < 8; nt++) {
                const uint32_t* bph = &bh[(nt >> 1) * 4 + (nt & 1) * 2];
                const uint32_t* bpl = &bl[(nt >> 1) * 4 + (nt & 1) * 2];
                mma_f16(acc[nt], ah, bph);
                mma_f16(acc[nt], ah, bpl);
            }
        }
        __syncthreads();
    }

    const int rl = row0 + w * 16 + (lane >> 2);
    if (mode == 2) {
        // v^T fp16 single
        const int b = rl / SEQ, s = rl % SEQ;
#pragma unroll
        for (int nt = 0; nt < 8; nt++) {
            int c = nt * 8 + (lane & 3) * 2;
#pragma unroll
            for (int e = 0; e < 2; e++) {
                g_vt[((size_t)b * HS + c + e) * SEQ + s]     = __float2half_rn(acc[nt][e]);
                g_vt[((size_t)b * HS + c + e) * SEQ + s + 8] = __float2half_rn(acc[nt][2 + e]);
            }
        }
    } else if (mode == 0) {
        // q fp16 single
#pragma unroll
        for (int nt = 0; nt < 8; nt++) {
            int c = nt * 8 + (lane & 3) * 2;
            *(uint32_t*)(g_q + (size_t)rl * HS + c) =
                packh2(__float2half_rn(acc[nt][0]), __float2half_rn(acc[nt][1]));
            *(uint32_t*)(g_q + (size_t)(rl + 8) * HS + c) =
                packh2(__float2half_rn(acc[nt][2]), __float2half_rn(acc[nt][3]));
        }
    } else {
        // k split hi/lo
#pragma unroll
        for (int nt = 0; nt < 8; nt++) {
            int c = nt * 8 + (lane & 3) * 2;
            __half h0, l0, h1, l1;
            fsplith(acc[nt][0], h0, l0); fsplith(acc[nt][1], h1, l1);
            *(uint32_t*)(g_kh + (size_t)rl * HS + c) = packh2(h0, h1);
            *(uint32_t*)(g_kl + (size_t)rl * HS + c) = packh2(l0, l1);
            fsplith(acc[nt][2], h0, l0); fsplith(acc[nt][3], h1, l1);
            *(uint32_t*)(g_kh + (size_t)(rl + 8) * HS + c) = packh2(h0, h1);
            *(uint32_t*)(g_kl + (size_t)(rl + 8) * HS + c) = packh2(l0, l1);
        }
    }
}

// =================================================================
// Kernel 3: split-KV causal flash attention, fp16.
// QK = q*(kh+kl); PV = (ph+pl)*vh. 4 KV buffers, 3-deep cp.async.
// =================================================================
#define AST 72
#define OFF_Q 0
#define OFF_BUF 18432
#define BUF_STRIDE 27648
#define ARR_STRIDE 9216
#define ATTN_SMEM (18432 + 4 * 27648)

__global__ __launch_bounds__(256, 1) void attn_mma()
{
    extern __shared__ __align__(16) char sm[];
    const uint32_t sb = s2u(sm);
    const int tid = threadIdx.x, lane = tid & 31, w = tid >> 5;
    const int b = blockIdx.y;
    const int qt   = 15 - ((int)blockIdx.x >> 1);
    const int half = (int)blockIdx.x & 1;
    const int k0 = half ? (qt + 1) : 0;
    const int k1 = half ? (2 * qt + 2) : (qt + 1);
    const int part = ((b * 16 + qt) * 2) + half;

    const __half* Qg  = g_q  + ((size_t)b * SEQ + qt * 128) * HS;
    const __half* Kh0 = g_kh + (size_t)b * SEQ * HS;
    const __half* Kl0 = g_kl + (size_t)b * SEQ * HS;
    const __half* Vt0 = g_vt + (size_t)b * HS * SEQ;

    // group 0: Q tile (128 x 64 fp16)
#pragma unroll
    for (int it = 0; it < 4; it++) {
        int idx = tid + it * 256, r = idx >> 3, q = idx & 7;
        cpa16(sb + OFF_Q + (r * AST + q * 8) * 2, Qg + (size_t)r * HS + q * 8);
    }
    CP_COMMIT();

    auto issue_kv = [&](int kt) {
        if (kt < k1) {
            uint32_t base = sb + OFF_BUF + ((kt - k0) & 3) * BUF_STRIDE;
#pragma unroll
            for (int it = 0; it < 6; it++) {
                int idx = tid + it * 256;            // 1536 chunks
                int a = idx >> 9, rem = idx & 511;
                int r = rem >> 3, q = rem & 7;
                const __half* src;
                if (a == 0)      src = Kh0 + (size_t)(kt * 64 + r) * HS + q * 8;
                else if (a == 1) src = Kl0 + (size_t)(kt * 64 + r) * HS + q * 8;
                else             src = Vt0 + (size_t)r * SEQ + kt * 64 + q * 8;
                cpa16(base + a * ARR_STRIDE + (r * AST + q * 8) * 2, src);
            }
        }
        CP_COMMIT();
    };
    issue_kv(k0);
    issue_kv(k0 + 1);
    issue_kv(k0 + 2);

    CP_WAIT3();            // Q complete
    __syncthreads();

    const uint32_t laneA = (uint32_t)((((lane & 7) + (((lane >> 3) & 1) << 3)) * AST + ((lane >> 4) << 3)) * 2);
    const uint32_t laneB = (uint32_t)((((lane & 7) + ((lane >> 4) << 3)) * AST + (((lane >> 3) & 1) << 3)) * 2);

    // persistent q fragments
    uint32_t qh[4][4];
#pragma unroll
    for (int ks = 0; ks < 4; ks++)
        ldsm4(qh[ks], sb + OFF_Q + (uint32_t)((w * 16 * AST + ks * 16) * 2) + laneA);

    float O[8][4];
#pragma unroll
    for (int nt = 0; nt < 8; nt++)
#pragma unroll
        for (int e = 0; e < 4; e++) O[nt][e] = 0.0f;
    float mr0 = -1e30f, mr1 = -1e30f, lr0 = 0.0f, lr1 = 0.0f;

    for (int kt = k0; kt < k1; kt++) {
        const int bf = (kt - k0) & 3;

        CP_WAIT2();
        __syncthreads();
        issue_kv(kt + 3);

        if (kt * 64 <= qt * 128 + w * 16 + 15) {   // skip fully-masked warp-tiles

        const uint32_t kbH = sb + OFF_BUF + bf * BUF_STRIDE;
        const uint32_t kbL = kbH + ARR_STRIDE;
        const uint32_t vbH = kbH + 2 * ARR_STRIDE;

        // ---- S = q (kh + kl) ----
        float s[8][4];
#pragma unroll
        for (int nt = 0; nt < 8; nt++)
#pragma unroll
            for (int e = 0; e < 4; e++) s[nt][e] = 0.0f;

#pragma unroll
        for (int ks = 0; ks < 4; ks++) {
            uint32_t bh[16], bl[16];
#pragma unroll
            for (int p = 0; p < 4; p++) {
                ldsm4(&bh[p * 4], kbH + (uint32_t)((p * 16 * AST + ks * 16) * 2) + laneB);
                ldsm4(&bl[p * 4], kbL + (uint32_t)((p * 16 * AST + ks * 16) * 2) + laneB);
            }
#pragma unroll
            for (int nt = 0; nt < 8; nt++) {
                const uint32_t* bph = &bh[(nt >> 1) * 4 + (nt & 1) * 2];
                const uint32_t* bpl = &bl[(nt >> 1) * 4 + (nt & 1) * 2];
                mma_f16(s[nt], qh[ks], bph);
                mma_f16(s[nt], qh[ks], bpl);
            }
        }

        // ---- causal mask ----
        if (kt >= 2 * qt) {
            int lim = qt * 128 + w * 16 + (lane >> 2) - kt * 64;
#pragma unroll
            for (int nt = 0; nt < 8; nt++) {
                int c = nt * 8 + (lane & 3) * 2;
                if (c     > lim)     s[nt][0] = -1e30f;
                if (c + 1 > lim)     s[nt][1] = -1e30f;
                if (c     > lim + 8) s[nt][2] = -1e30f;
                if (c + 1 > lim + 8) s[nt][3] = -1e30f;
            }
        }

        // ---- online softmax (exp2 domain) ----
        float rm0 = -1e30f, rm1 = -1e30f;
#pragma unroll
        for (int nt = 0; nt < 8; nt++) {
            rm0 = fmaxf(rm0, fmaxf(s[nt][0], s[nt][1]));
            rm1 = fmaxf(rm1, fmaxf(s[nt][2], s[nt][3]));
        }
        rm0 = fmaxf(rm0, __shfl_xor_sync(0xffffffffu, rm0, 1));
        rm0 = fmaxf(rm0, __shfl_xor_sync(0xffffffffu, rm0, 2));
        rm1 = fmaxf(rm1, __shfl_xor_sync(0xffffffffu, rm1, 1));
        rm1 = fmaxf(rm1, __shfl_xor_sync(0xffffffffu, rm1, 2));
        float mn0 = fmaxf(mr0, rm0), mn1 = fmaxf(mr1, rm1);
        float al0 = ex2(mr0 - mn0), al1 = ex2(mr1 - mn1);
        mr0 = mn0; mr1 = mn1;

        float rs0 = 0.0f, rs1 = 0.0f;
#pragma unroll
        for (int nt = 0; nt < 8; nt++) {
            s[nt][0] = ex2(s[nt][0] - mn0);
            s[nt][1] = ex2(s[nt][1] - mn0);
            s[nt][2] = ex2(s[nt][2] - mn1);
            s[nt][3] = ex2(s[nt][3] - mn1);
            rs0 += s[nt][0] + s[nt][1];
            rs1 += s[nt][2] + s[nt][3];
        }
        rs0 += __shfl_xor_sync(0xffffffffu, rs0, 1);
        rs0 += __shfl_xor_sync(0xffffffffu, rs0, 2);
        rs1 += __shfl_xor_sync(0xffffffffu, rs1, 1);
        rs1 += __shfl_xor_sync(0xffffffffu, rs1, 2);
        lr0 = lr0 * al0 + rs0;
        lr1 = lr1 * al1 + rs1;
#pragma unroll
        for (int nt = 0; nt < 8; nt++) {
            O[nt][0] *= al0; O[nt][1] *= al0;
            O[nt][2] *= al1; O[nt][3] *= al1;
        }

        // ---- O += (Ph + Pl) @ Vh ----
#pragma unroll
        for (int ks = 0; ks < 4; ks++) {
            uint32_t ph[4], pl[4];
            {
                int t0 = 2 * ks, t1 = 2 * ks + 1;
                __half ha, la, hb, lb;
                fsplith(s[t0][0], ha, la); fsplith(s[t0][1], hb, lb);
                ph[0] = packh2(ha, hb); pl[0] = packh2(la, lb);
                fsplith(s[t0][2], ha, la); fsplith(s[t0][3], hb, lb);
                ph[1] = packh2(ha, hb); pl[1] = packh2(la, lb);
                fsplith(s[t1][0], ha, la); fsplith(s[t1][1], hb, lb);
                ph[2] = packh2(ha, hb); pl[2] = packh2(la, lb);
                fsplith(s[t1][2], ha, la); fsplith(s[t1][3], hb, lb);
                ph[3] = packh2(ha, hb); pl[3] = packh2(la, lb);
            }
            uint32_t vh[16];
#pragma unroll
            for (int p = 0; p < 4; p++)
                ldsm4(&vh[p * 4], vbH + (uint32_t)((p * 16 * AST + ks * 16) * 2) + laneB);
#pragma unroll
            for (int nt = 0; nt < 8; nt++) {
                const uint32_t* vph = &vh[(nt >> 1) * 4 + (nt & 1) * 2];
                mma_f16(O[nt], ph, vph);
                mma_f16(O[nt], pl, vph);
            }
        }

        } // end skip
    }

    // ---- epilogue ----
    int r0 = w * 16 + (lane >> 2);
#pragma unroll
    for (int nt = 0; nt < 8; nt++) {
        int c = nt * 8 + (lane & 3) * 2;
        *(float2*)(&g_pO[part][r0][c])     = make_float2(O[nt][0], O[nt][1]);
        *(float2*)(&g_pO[part][r0 + 8][c]) = make_float2(O[nt][2], O[nt][3]);
    }
    if ((lane & 3) == 0) {
        g_pm[part][r0] = mr0;     g_pl[part][r0] = lr0;
        g_pm[part][r0 + 8] = mr1; g_pl[part][r0 + 8] = lr1;
    }
}

// =================================================================
// Kernel 4: combine.
// =================================================================
__global__ __launch_bounds__(256) void combine(float* __restrict__ out)
{
    const int pair  = blockIdx.x >> 3;
    const int chunk = blockIdx.x & 7;
    const int r = chunk * 16 + (threadIdx.x >> 4);
    const int c = (threadIdx.x & 15) * 4;
    const int p0 = pair * 2, p1 = p0 + 1;

    float m0 = g_pm[p0][r], l0 = g_pl[p0][r];
    float m1 = g_pm[p1][r], l1 = g_pl[p1][r];
    float M  = fmaxf(m0, m1);
    float w0 = ex2(m0 - M), w1 = ex2(m1 - M);
    float inv = 1.0f / (w0 * l0 + w1 * l1);
    float c0 = w0 * inv, c1 = w1 * inv;

    const int b = pair >> 4, qt = pair & 15;
    float4 a = *(const float4*)(&g_pO[p0][r][c]);
    float4 d = *(const float4*)(&g_pO[p1][r][c]);
    float* op = out + ((size_t)b * SEQ + qt * 128 + r) * HS + c;
    *(float4*)op = make_float4(a.x * c0 + d.x * c1, a.y * c0 + d.y * c1,
                               a.z * c0 + d.z * c1, a.w * c0 + d.w * c1);
}

// =================================================================
extern "C" void kernel_launch(void* const* d_in, const int* in_sizes, int n_in,
                              void* d_out, int out_size)
{
    (void)in_sizes; (void)n_in; (void)out_size;
    const float* query = (const float*)d_in[0];
    const float* key   = (const float*)d_in[1];
    const float* value = (const float*)d_in[2];
    const float* Wq    = (const float*)d_in[3];
    const float* Wk    = (const float*)d_in[4];
    const float* Wv    = (const float*)d_in[5];

    prep_w<<<dim3(256, 3, 1), 256>>>(Wq, Wk, Wv);

    proj_mma<<<dim3(128, 3, 1), 256>>>(query, key, value);

    cudaFuncSetAttribute(attn_mma, cudaFuncAttributeMaxDynamicSharedMemorySize, ATTN_SMEM);
    attn_mma<<<dim3(32, NB, 1), 256, ATTN_SMEM>>>();

    combine<<<NB * 16 * 8, 256>>>((float*)d_out);
}